// round 16
// baseline (speedup 1.0000x reference)
#include <cuda_runtime.h>
#include <cuda_bf16.h>
#include <cuda_fp16.h>
#include <cstdint>

#define NN 50000
#define EE 600000
#define DD 128
#define HH 32
#define NTILES ((NN + 63) / 64)   // 782

// ---------------------------------------------------------------------------
// Scratch
// ---------------------------------------------------------------------------
__device__ float4  g_xw4[NN * (DD / 4)];  // xw = x @ W_gcn (fp32, self term)
__device__ __half2 g_xwh2[NN * (DD / 2)]; // dinv[row]*xw[row] fp16 (gather)
__device__ float   g_dinv[NN];
__device__ int     g_deg[NN];             // zeroed by k_aggmlp of PREVIOUS call
__device__ int     g_excl[NN];
__device__ int     g_bsum[256];
__device__ int     g_rowstart[NN];        // doubles as scatter cursor:
                                          // post-scatter, rowstart[n] == orig rowstart[n+1]
__device__ int     g_srow[EE];

// ---------------------------------------------------------------------------
// K1: in-degree histogram — 2 edges/thread (int2)
// ---------------------------------------------------------------------------
__global__ void k_count(const int* __restrict__ ei) {
    int t = blockIdx.x * blockDim.x + threadIdx.x;
    if (t >= EE / 2) return;
    int2 c = __ldg(&reinterpret_cast<const int2*>(ei + EE)[t]);
    atomicAdd(&g_deg[c.x], 1);
    atomicAdd(&g_deg[c.y], 1);
}

// ---------------------------------------------------------------------------
// K2a: per-block scan + dinv + publish block sums
// ---------------------------------------------------------------------------
__global__ __launch_bounds__(256) void k_scan1() {
    __shared__ int wsum[8];
    const int tid  = threadIdx.x;
    const int lane = tid & 31;
    const int w    = tid >> 5;
    const int i    = blockIdx.x * 256 + tid;

    int v = (i < NN) ? g_deg[i] : 0;
    int incl = v;
    #pragma unroll
    for (int d = 1; d < 32; d <<= 1) {
        int t = __shfl_up_sync(0xFFFFFFFFu, incl, d);
        if (lane >= d) incl += t;
    }
    if (lane == 31) wsum[w] = incl;
    __syncthreads();
    if (w == 0 && lane < 8) {
        int s = wsum[lane];
        #pragma unroll
        for (int d = 1; d < 8; d <<= 1) {
            int t = __shfl_up_sync(0xFFu, s, d);
            if (lane >= d) s += t;
        }
        wsum[lane] = s;
    }
    __syncthreads();
    int offs = (w > 0) ? wsum[w - 1] : 0;
    if (i < NN) {
        g_excl[i] = offs + incl - v;
        g_dinv[i] = rsqrtf((float)(v + 1));
    }
    if (tid == 255) g_bsum[blockIdx.x] = wsum[7];
}

// ---------------------------------------------------------------------------
// K2b: rowstart[i] = exclusive_prefix(deg)[i]
// ---------------------------------------------------------------------------
__global__ __launch_bounds__(256) void k_scan23(int nblk) {
    __shared__ int s_boff;
    const int tid  = threadIdx.x;
    const int bid  = blockIdx.x;

    if (tid < 32) {
        int acc = 0;
        #pragma unroll
        for (int p = 0; p < 7; p++) {
            int j = p * 32 + tid;
            if (j < bid && j < nblk) acc += g_bsum[j];
        }
        #pragma unroll
        for (int off = 16; off > 0; off >>= 1)
            acc += __shfl_xor_sync(0xFFFFFFFFu, acc, off);
        if (tid == 0) s_boff = acc;
    }
    __syncthreads();

    int i = bid * 256 + tid;
    if (i < NN) g_rowstart[i] = g_excl[i] + s_boff;
}

// ---------------------------------------------------------------------------
// K3: bucket-scatter — 2 edges/thread; cursor IS rowstart (advances in place)
// ---------------------------------------------------------------------------
__global__ void k_scatter(const int* __restrict__ ei) {
    int t = blockIdx.x * blockDim.x + threadIdx.x;
    if (t >= EE / 2) return;
    int2 r = __ldg(&reinterpret_cast<const int2*>(ei)[t]);
    int2 c = __ldg(&reinterpret_cast<const int2*>(ei + EE)[t]);
    int p0 = atomicAdd(&g_rowstart[c.x], 1);
    int p1 = atomicAdd(&g_rowstart[c.y], 1);
    g_srow[p0] = r.x;
    g_srow[p1] = r.y;
}

// ---------------------------------------------------------------------------
// K4: xw = x @ W via mma.sync tf32.
//     Epilogue: fp32 xw (self term) + fp16 dinv[row]*xw (gather matrix).
//     REQUIRES g_dinv ready (launched after k_scan1).
// ---------------------------------------------------------------------------
__device__ __forceinline__ uint32_t f2tf32(float f) {
    uint32_t r;
    asm("cvt.rna.tf32.f32 %0, %1;" : "=r"(r) : "f"(f));
    return r;
}

#define XS_STRIDE 132
#define WS_STRIDE 136

__global__ __launch_bounds__(128) void k_gemm_mma(const float* __restrict__ x,
                                                  const float* __restrict__ W) {
    extern __shared__ float smem[];
    float* xs = smem;
    float* ws = smem + 64 * XS_STRIDE;

    const int tid  = threadIdx.x;
    const int lane = tid & 31;
    const int warp = tid >> 5;
    const int row0 = blockIdx.x * 64;

    #pragma unroll
    for (int it = 0; it < 32; it++) {
        int idx = tid + it * 128;
        int k  = idx >> 5;
        int c4 = (idx & 31) * 4;
        float4 v = __ldg(reinterpret_cast<const float4*>(&W[k * DD + c4]));
        float* d = &ws[k * WS_STRIDE + c4];
        d[0] = __uint_as_float(f2tf32(v.x));
        d[1] = __uint_as_float(f2tf32(v.y));
        d[2] = __uint_as_float(f2tf32(v.z));
        d[3] = __uint_as_float(f2tf32(v.w));
    }
    #pragma unroll
    for (int it = 0; it < 16; it++) {
        int idx = tid + it * 128;
        int r  = idx >> 5;
        int c4 = (idx & 31) * 4;
        int g  = row0 + r;
        float4 v = make_float4(0.f, 0.f, 0.f, 0.f);
        if (g < NN) v = __ldg(reinterpret_cast<const float4*>(&x[g * DD + c4]));
        float* d = &xs[r * XS_STRIDE + c4];
        d[0] = __uint_as_float(f2tf32(v.x));
        d[1] = __uint_as_float(f2tf32(v.y));
        d[2] = __uint_as_float(f2tf32(v.z));
        d[3] = __uint_as_float(f2tf32(v.w));
    }
    __syncthreads();

    const int g  = lane >> 2;
    const int tg = lane & 3;
    const int wrow = warp * 16;

    float acc[16][4];
    #pragma unroll
    for (int nt = 0; nt < 16; nt++)
        #pragma unroll
        for (int q = 0; q < 4; q++) acc[nt][q] = 0.f;

    #pragma unroll
    for (int kk = 0; kk < DD; kk += 8) {
        uint32_t a0 = __float_as_uint(xs[(wrow + g    ) * XS_STRIDE + kk + tg    ]);
        uint32_t a1 = __float_as_uint(xs[(wrow + g + 8) * XS_STRIDE + kk + tg    ]);
        uint32_t a2 = __float_as_uint(xs[(wrow + g    ) * XS_STRIDE + kk + tg + 4]);
        uint32_t a3 = __float_as_uint(xs[(wrow + g + 8) * XS_STRIDE + kk + tg + 4]);
        #pragma unroll
        for (int nt = 0; nt < 16; nt++) {
            uint32_t b0 = __float_as_uint(ws[(kk + tg    ) * WS_STRIDE + nt * 8 + g]);
            uint32_t b1 = __float_as_uint(ws[(kk + tg + 4) * WS_STRIDE + nt * 8 + g]);
            asm volatile(
                "mma.sync.aligned.m16n8k8.row.col.f32.tf32.tf32.f32 "
                "{%0,%1,%2,%3}, {%4,%5,%6,%7}, {%8,%9}, {%0,%1,%2,%3};"
                : "+f"(acc[nt][0]), "+f"(acc[nt][1]), "+f"(acc[nt][2]), "+f"(acc[nt][3])
                : "r"(a0), "r"(a1), "r"(a2), "r"(a3), "r"(b0), "r"(b1));
        }
    }

    float* xw = reinterpret_cast<float*>(g_xw4);
    int r_lo = row0 + wrow + g;
    int r_hi = r_lo + 8;
    float d_lo = (r_lo < NN) ? g_dinv[r_lo] : 0.f;
    float d_hi = (r_hi < NN) ? g_dinv[r_hi] : 0.f;
    #pragma unroll
    for (int nt = 0; nt < 16; nt++) {
        int col = nt * 8 + 2 * tg;
        if (r_lo < NN) {
            *reinterpret_cast<float2*>(&xw[r_lo * DD + col]) =
                make_float2(acc[nt][0], acc[nt][1]);
            g_xwh2[r_lo * 64 + (col >> 1)] =
                __floats2half2_rn(acc[nt][0] * d_lo, acc[nt][1] * d_lo);
        }
        if (r_hi < NN) {
            *reinterpret_cast<float2*>(&xw[r_hi * DD + col]) =
                make_float2(acc[nt][2], acc[nt][3]);
            g_xwh2[r_hi * 64 + (col >> 1)] =
                __floats2half2_rn(acc[nt][2] * d_hi, acc[nt][3] * d_hi);
        }
    }
}

// ---------------------------------------------------------------------------
// K5: PERSISTENT blocks, 512 threads; each block loops over 64-node tiles.
//   Per-tile body identical to the verified config. Post-scatter rowstart
//   semantics: node n's edge range is [rowstart[n-1], rowstart[n]).
// ---------------------------------------------------------------------------
#define HS 132
#define SS 36

__device__ __forceinline__ void acc_row(float4& a, int row, int lane) {
    uint2 u = __ldg(reinterpret_cast<const uint2*>(&g_xwh2[row * 64 + lane * 2]));
    float2 fa = __half22float2(*reinterpret_cast<__half2*>(&u.x));
    float2 fb = __half22float2(*reinterpret_cast<__half2*>(&u.y));
    a.x += fa.x; a.y += fa.y; a.z += fb.x; a.w += fb.y;
}

__global__ __launch_bounds__(512) void k_aggmlp(const float* __restrict__ x,
                                                const float* __restrict__ b_gcn,
                                                const float* __restrict__ w1,
                                                const float* __restrict__ b1,
                                                const float* __restrict__ w2,
                                                const float* __restrict__ b2,
                                                const float* __restrict__ w3,
                                                const float* __restrict__ b3,
                                                float* __restrict__ out) {
    extern __shared__ float smem[];
    float* hs   = smem;                    // [64][HS]
    float* s1s  = smem + 64 * HS;          // [64][SS]
    float* s2s  = s1s + 64 * SS;           // [64][SS]
    int*   s_rs = reinterpret_cast<int*>(s2s + 64 * SS);  // [65]
    float* s_dv = reinterpret_cast<float*>(s_rs + 68);    // [64]

    const int tid  = threadIdx.x;
    const int lane = tid & 31;
    const int warp = tid >> 5;             // 0..15
    const int g    = lane >> 2;
    const int tg   = lane & 3;

    float4 bg = __ldg(&reinterpret_cast<const float4*>(b_gcn)[lane]);

    for (int tile = blockIdx.x; tile < NTILES; tile += gridDim.x) {
        const int nbase = tile * 64;

        if (tid < 64 && nbase + tid < NN) {
            g_deg[nbase + tid] = 0;        // for NEXT invocation
            s_dv[tid] = g_dinv[nbase + tid];
        }
        // s_rs[k] = orig rowstart[nbase+k] = post-scatter rowstart[nbase+k-1]
        if (tid < 65 && nbase + tid <= NN) {
            int idx = nbase + tid - 1;
            s_rs[tid] = (idx >= 0) ? g_rowstart[idx] : 0;
        }
        __syncthreads();

        // ---- Phase A: 4 nodes per warp; 1-ahead srow prefetch ----
        const int r0 = warp * 4;
        int e0c = 0, cntc = 0, src = 0;
        if (nbase + r0 < NN) {
            e0c  = s_rs[r0];
            cntc = s_rs[r0 + 1] - e0c;
            src  = (lane < cntc) ? __ldg(&g_srow[e0c + lane]) : 0;
        }

        #pragma unroll 1
        for (int i = 0; i < 4; i++) {
            int r = r0 + i;
            int n = nbase + r;

            int e0n = 0, cntn = 0, srn = 0;
            if (i < 3 && nbase + r + 1 < NN) {
                e0n  = s_rs[r + 1];
                cntn = s_rs[r + 2] - e0n;
                srn  = (lane < cntn) ? __ldg(&g_srow[e0n + lane]) : 0;
            }

            if (n >= NN) {
                *reinterpret_cast<float4*>(&hs[r * HS + lane * 4]) =
                    make_float4(0.f, 0.f, 0.f, 0.f);
                e0c = e0n; cntc = cntn; src = srn;
                continue;
            }

            float4 wv = g_xw4[n * 32 + lane];
            float4 xv = reinterpret_cast<const float4*>(x)[n * 32 + lane];
            float  d  = s_dv[r];

            float4 a0 = make_float4(0.f, 0.f, 0.f, 0.f);
            float4 a1 = make_float4(0.f, 0.f, 0.f, 0.f);
            float4 a2 = make_float4(0.f, 0.f, 0.f, 0.f);
            float4 a3 = make_float4(0.f, 0.f, 0.f, 0.f);

            int m = cntc < 32 ? cntc : 32;
            int j = 0;
            for (; j + 3 < m; j += 4) {
                int ra = __shfl_sync(0xFFFFFFFFu, src, j);
                int rb = __shfl_sync(0xFFFFFFFFu, src, j + 1);
                int rc = __shfl_sync(0xFFFFFFFFu, src, j + 2);
                int rd = __shfl_sync(0xFFFFFFFFu, src, j + 3);
                acc_row(a0, ra, lane);
                acc_row(a1, rb, lane);
                acc_row(a2, rc, lane);
                acc_row(a3, rd, lane);
            }
            for (; j < m; j++) {
                int ra = __shfl_sync(0xFFFFFFFFu, src, j);
                acc_row(a0, ra, lane);
            }
            for (int e = e0c + 32; e < e0c + cntc; e++)   // rare deg>32 tail
                acc_row(a0, g_srow[e], lane);

            a0.x += a1.x + a2.x + a3.x;
            a0.y += a1.y + a2.y + a3.y;
            a0.z += a1.z + a2.z + a3.z;
            a0.w += a1.w + a2.w + a3.w;

            float h0 = fmaxf(fmaf(d, a0.x, d * d * wv.x) + bg.x, 0.f) + xv.x;
            float h1 = fmaxf(fmaf(d, a0.y, d * d * wv.y) + bg.y, 0.f) + xv.y;
            float h2 = fmaxf(fmaf(d, a0.z, d * d * wv.z) + bg.z, 0.f) + xv.z;
            float h3 = fmaxf(fmaf(d, a0.w, d * d * wv.w) + bg.w, 0.f) + xv.w;

            *reinterpret_cast<float4*>(&hs[r * HS + lane * 4]) =
                make_float4(__uint_as_float(f2tf32(h0)), __uint_as_float(f2tf32(h1)),
                            __uint_as_float(f2tf32(h2)), __uint_as_float(f2tf32(h3)));

            e0c = e0n; cntc = cntn; src = srn;
        }
        __syncthreads();

        // ---- Phase B1: layer1 [64x128]@[128x32] ----
        if (warp < 4) {
            const int m0 = warp * 16;
            float acc[4][4];
            #pragma unroll
            for (int nt = 0; nt < 4; nt++)
                #pragma unroll
                for (int q = 0; q < 4; q++) acc[nt][q] = 0.f;

            #pragma unroll
            for (int kk = 0; kk < DD; kk += 8) {
                uint32_t fa0 = __float_as_uint(hs[(m0 + g    ) * HS + kk + tg    ]);
                uint32_t fa1 = __float_as_uint(hs[(m0 + g + 8) * HS + kk + tg    ]);
                uint32_t fa2 = __float_as_uint(hs[(m0 + g    ) * HS + kk + tg + 4]);
                uint32_t fa3 = __float_as_uint(hs[(m0 + g + 8) * HS + kk + tg + 4]);
                #pragma unroll
                for (int nt = 0; nt < 4; nt++) {
                    uint32_t b0 = f2tf32(__ldg(&w1[(kk + tg    ) * HH + nt * 8 + g]));
                    uint32_t b1r = f2tf32(__ldg(&w1[(kk + tg + 4) * HH + nt * 8 + g]));
                    asm volatile(
                        "mma.sync.aligned.m16n8k8.row.col.f32.tf32.tf32.f32 "
                        "{%0,%1,%2,%3}, {%4,%5,%6,%7}, {%8,%9}, {%0,%1,%2,%3};"
                        : "+f"(acc[nt][0]), "+f"(acc[nt][1]), "+f"(acc[nt][2]), "+f"(acc[nt][3])
                        : "r"(fa0), "r"(fa1), "r"(fa2), "r"(fa3), "r"(b0), "r"(b1r));
                }
            }
            #pragma unroll
            for (int nt = 0; nt < 4; nt++) {
                int c0 = nt * 8 + 2 * tg;
                float bb0 = __ldg(&b1[c0]);
                float bb1 = __ldg(&b1[c0 + 1]);
                s1s[(m0 + g    ) * SS + c0    ] = __uint_as_float(f2tf32(fmaxf(acc[nt][0] + bb0, 0.f)));
                s1s[(m0 + g    ) * SS + c0 + 1] = __uint_as_float(f2tf32(fmaxf(acc[nt][1] + bb1, 0.f)));
                s1s[(m0 + g + 8) * SS + c0    ] = __uint_as_float(f2tf32(fmaxf(acc[nt][2] + bb0, 0.f)));
                s1s[(m0 + g + 8) * SS + c0 + 1] = __uint_as_float(f2tf32(fmaxf(acc[nt][3] + bb1, 0.f)));
            }
        }
        __syncthreads();

        // ---- Phase B2: layer2 [64x32]@[32x32] ----
        if (warp < 4) {
            const int m0 = warp * 16;
            float acc[4][4];
            #pragma unroll
            for (int nt = 0; nt < 4; nt++)
                #pragma unroll
                for (int q = 0; q < 4; q++) acc[nt][q] = 0.f;

            #pragma unroll
            for (int kk = 0; kk < HH; kk += 8) {
                uint32_t fa0 = __float_as_uint(s1s[(m0 + g    ) * SS + kk + tg    ]);
                uint32_t fa1 = __float_as_uint(s1s[(m0 + g + 8) * SS + kk + tg    ]);
                uint32_t fa2 = __float_as_uint(s1s[(m0 + g    ) * SS + kk + tg + 4]);
                uint32_t fa3 = __float_as_uint(s1s[(m0 + g + 8) * SS + kk + tg + 4]);
                #pragma unroll
                for (int nt = 0; nt < 4; nt++) {
                    uint32_t b0 = f2tf32(__ldg(&w2[(kk + tg    ) * HH + nt * 8 + g]));
                    uint32_t b1r = f2tf32(__ldg(&w2[(kk + tg + 4) * HH + nt * 8 + g]));
                    asm volatile(
                        "mma.sync.aligned.m16n8k8.row.col.f32.tf32.tf32.f32 "
                        "{%0,%1,%2,%3}, {%4,%5,%6,%7}, {%8,%9}, {%0,%1,%2,%3};"
                        : "+f"(acc[nt][0]), "+f"(acc[nt][1]), "+f"(acc[nt][2]), "+f"(acc[nt][3])
                        : "r"(fa0), "r"(fa1), "r"(fa2), "r"(fa3), "r"(b0), "r"(b1r));
                }
            }
            #pragma unroll
            for (int nt = 0; nt < 4; nt++) {
                int c0 = nt * 8 + 2 * tg;
                float bb0 = __ldg(&b2[c0]);
                float bb1 = __ldg(&b2[c0 + 1]);
                s2s[(m0 + g    ) * SS + c0    ] = fmaxf(acc[nt][0] + bb0, 0.f);
                s2s[(m0 + g    ) * SS + c0 + 1] = fmaxf(acc[nt][1] + bb1, 0.f);
                s2s[(m0 + g + 8) * SS + c0    ] = fmaxf(acc[nt][2] + bb0, 0.f);
                s2s[(m0 + g + 8) * SS + c0 + 1] = fmaxf(acc[nt][3] + bb1, 0.f);
            }
        }
        __syncthreads();

        // ---- Phase C: layer3 ----
        if (tid < 64) {
            int n = nbase + tid;
            if (n < NN) {
                float p = 0.f;
                #pragma unroll
                for (int j = 0; j < HH; j++)
                    p = fmaf(s2s[tid * SS + j], __ldg(&w3[j]), p);
                out[n] = p + __ldg(&b3[0]);
            }
        }
        __syncthreads();   // protect smem staging of next tile
    }
}

// ---------------------------------------------------------------------------
// launch — count+scan1 first; GEMM (needs dinv) overlaps scan23+scatter;
//          persistent aggmlp grid sized to exact occupancy (no partial wave)
// ---------------------------------------------------------------------------
extern "C" void kernel_launch(void* const* d_in, const int* in_sizes, int n_in,
                              void* d_out, int out_size) {
    const float* x     = (const float*)d_in[0];
    const int*   ei    = (const int*)  d_in[1];
    const float* W_gcn = (const float*)d_in[2];
    const float* b_gcn = (const float*)d_in[3];
    const float* w1    = (const float*)d_in[4];
    const float* b1    = (const float*)d_in[5];
    const float* w2    = (const float*)d_in[6];
    const float* b2    = (const float*)d_in[7];
    const float* w3    = (const float*)d_in[8];
    const float* b3    = (const float*)d_in[9];
    float* out = (float*)d_out;

    const int smem_gemm = (64 * XS_STRIDE + 128 * WS_STRIDE) * sizeof(float);
    const int smem_agg  = (64 * HS + 2 * 64 * SS) * sizeof(float) + 68 * 4 + 64 * 4;
    static cudaStream_t s1 = nullptr;
    static cudaEvent_t evDinv, evGemm;
    static int grid_agg = 0;
    if (s1 == nullptr) {
        cudaFuncSetAttribute(k_gemm_mma, cudaFuncAttributeMaxDynamicSharedMemorySize,
                             smem_gemm);
        cudaFuncSetAttribute(k_aggmlp, cudaFuncAttributeMaxDynamicSharedMemorySize,
                             smem_agg);
        cudaStreamCreateWithFlags(&s1, cudaStreamNonBlocking);
        cudaEventCreateWithFlags(&evDinv, cudaEventDisableTiming);
        cudaEventCreateWithFlags(&evGemm, cudaEventDisableTiming);

        int dev = 0, nsm = 0, occ = 0;
        cudaGetDevice(&dev);
        cudaDeviceGetAttribute(&nsm, cudaDevAttrMultiProcessorCount, dev);
        cudaOccupancyMaxActiveBlocksPerMultiprocessor(&occ, k_aggmlp, 512, smem_agg);
        if (occ < 1) occ = 1;
        grid_agg = nsm * occ;
        if (grid_agg > NTILES) grid_agg = NTILES;
    }

    const int nblk = (NN + 255) / 256;  // 196

    k_count  <<<(EE / 2 + 255) / 256, 256>>>(ei);
    k_scan1  <<<nblk, 256>>>();
    cudaEventRecord(evDinv, 0);                 // dinv ready

    // side stream: GEMM with premultiplied fp16 epilogue
    cudaStreamWaitEvent(s1, evDinv, 0);
    k_gemm_mma<<<(NN + 63) / 64, 128, smem_gemm, s1>>>(x, W_gcn);
    cudaEventRecord(evGemm, s1);

    // main stream: finish CSR build in parallel with the GEMM
    k_scan23 <<<nblk, 256>>>(nblk);
    k_scatter<<<(EE / 2 + 255) / 256, 256>>>(ei);

    cudaStreamWaitEvent(0, evGemm, 0);
    k_aggmlp <<<grid_agg, 512, smem_agg>>>(x, b_gcn, w1, b1, w2, b2, w3, b3, out);
}

// round 17
// speedup vs baseline: 1.0758x; 1.0758x over previous
#include <cuda_runtime.h>
#include <cuda_bf16.h>
#include <cuda_fp16.h>
#include <cstdint>

#define NN 50000
#define EE 600000
#define DD 128
#define HH 32

// ---------------------------------------------------------------------------
// Scratch
// ---------------------------------------------------------------------------
__device__ float4  g_xw4[NN * (DD / 4)];  // xw = x @ W_gcn (fp32, self term)
__device__ __half2 g_xwh2[NN * (DD / 2)]; // dinv[row]*xw[row] fp16 (gather)
__device__ float   g_dinv[NN];
__device__ int     g_deg[NN];             // zeroed by k_aggmlp of PREVIOUS call
__device__ int     g_excl[NN];
__device__ int     g_bsum[256];
__device__ int     g_rowstart[NN + 1];
__device__ int     g_cursor[NN];
__device__ int     g_srow[EE];

// ---------------------------------------------------------------------------
// K1: in-degree histogram (1 edge/thread)
// ---------------------------------------------------------------------------
__global__ void k_count(const int* __restrict__ ei) {
    int i = blockIdx.x * blockDim.x + threadIdx.x;
    if (i >= EE) return;
    atomicAdd(&g_deg[__ldg(&ei[EE + i])], 1);
}

// ---------------------------------------------------------------------------
// K2a: per-block scan + dinv + publish block sums
// ---------------------------------------------------------------------------
__global__ __launch_bounds__(256) void k_scan1() {
    __shared__ int wsum[8];
    const int tid  = threadIdx.x;
    const int lane = tid & 31;
    const int w    = tid >> 5;
    const int i    = blockIdx.x * 256 + tid;

    int v = (i < NN) ? g_deg[i] : 0;
    int incl = v;
    #pragma unroll
    for (int d = 1; d < 32; d <<= 1) {
        int t = __shfl_up_sync(0xFFFFFFFFu, incl, d);
        if (lane >= d) incl += t;
    }
    if (lane == 31) wsum[w] = incl;
    __syncthreads();
    if (w == 0 && lane < 8) {
        int s = wsum[lane];
        #pragma unroll
        for (int d = 1; d < 8; d <<= 1) {
            int t = __shfl_up_sync(0xFFu, s, d);
            if (lane >= d) s += t;
        }
        wsum[lane] = s;
    }
    __syncthreads();
    int offs = (w > 0) ? wsum[w - 1] : 0;
    if (i < NN) {
        g_excl[i] = offs + incl - v;
        g_dinv[i] = rsqrtf((float)(v + 1));
    }
    if (tid == 255) g_bsum[blockIdx.x] = wsum[7];
}

// ---------------------------------------------------------------------------
// K2b: rowstart = excl + prefix(bsum); each block self-computes its prefix
// ---------------------------------------------------------------------------
__global__ __launch_bounds__(256) void k_scan23(int nblk) {
    __shared__ int s_boff;
    const int tid  = threadIdx.x;
    const int bid  = blockIdx.x;

    if (tid < 32) {
        int acc = 0;
        #pragma unroll
        for (int p = 0; p < 7; p++) {
            int j = p * 32 + tid;
            if (j < bid && j < nblk) acc += g_bsum[j];
        }
        #pragma unroll
        for (int off = 16; off > 0; off >>= 1)
            acc += __shfl_xor_sync(0xFFFFFFFFu, acc, off);
        if (tid == 0) s_boff = acc;
    }
    __syncthreads();

    int i = bid * 256 + tid;
    if (i < NN) {
        int r = g_excl[i] + s_boff;
        g_rowstart[i] = r;
        g_cursor[i]   = r;
    }
    if (i == 0) g_rowstart[NN] = EE;
}

// ---------------------------------------------------------------------------
// K3: bucket-scatter (1 edge/thread)
// ---------------------------------------------------------------------------
__global__ void k_scatter(const int* __restrict__ ei) {
    int i = blockIdx.x * blockDim.x + threadIdx.x;
    if (i >= EE) return;
    int row = __ldg(&ei[i]);
    int col = __ldg(&ei[EE + i]);
    int pos = atomicAdd(&g_cursor[col], 1);
    g_srow[pos] = row;
}

// ---------------------------------------------------------------------------
// K4: xw = x @ W via mma.sync tf32.
//     Epilogue: fp32 xw (self term) + fp16 dinv[row]*xw (gather matrix).
//     REQUIRES g_dinv ready (launched after k_scan1).
// ---------------------------------------------------------------------------
__device__ __forceinline__ uint32_t f2tf32(float f) {
    uint32_t r;
    asm("cvt.rna.tf32.f32 %0, %1;" : "=r"(r) : "f"(f));
    return r;
}

#define XS_STRIDE 132
#define WS_STRIDE 136

__global__ __launch_bounds__(128) void k_gemm_mma(const float* __restrict__ x,
                                                  const float* __restrict__ W) {
    extern __shared__ float smem[];
    float* xs = smem;
    float* ws = smem + 64 * XS_STRIDE;

    const int tid  = threadIdx.x;
    const int lane = tid & 31;
    const int warp = tid >> 5;
    const int row0 = blockIdx.x * 64;

    #pragma unroll
    for (int it = 0; it < 32; it++) {
        int idx = tid + it * 128;
        int k  = idx >> 5;
        int c4 = (idx & 31) * 4;
        float4 v = __ldg(reinterpret_cast<const float4*>(&W[k * DD + c4]));
        float* d = &ws[k * WS_STRIDE + c4];
        d[0] = __uint_as_float(f2tf32(v.x));
        d[1] = __uint_as_float(f2tf32(v.y));
        d[2] = __uint_as_float(f2tf32(v.z));
        d[3] = __uint_as_float(f2tf32(v.w));
    }
    #pragma unroll
    for (int it = 0; it < 16; it++) {
        int idx = tid + it * 128;
        int r  = idx >> 5;
        int c4 = (idx & 31) * 4;
        int g  = row0 + r;
        float4 v = make_float4(0.f, 0.f, 0.f, 0.f);
        if (g < NN) v = __ldg(reinterpret_cast<const float4*>(&x[g * DD + c4]));
        float* d = &xs[r * XS_STRIDE + c4];
        d[0] = __uint_as_float(f2tf32(v.x));
        d[1] = __uint_as_float(f2tf32(v.y));
        d[2] = __uint_as_float(f2tf32(v.z));
        d[3] = __uint_as_float(f2tf32(v.w));
    }
    __syncthreads();

    const int g  = lane >> 2;
    const int tg = lane & 3;
    const int wrow = warp * 16;

    float acc[16][4];
    #pragma unroll
    for (int nt = 0; nt < 16; nt++)
        #pragma unroll
        for (int q = 0; q < 4; q++) acc[nt][q] = 0.f;

    #pragma unroll
    for (int kk = 0; kk < DD; kk += 8) {
        uint32_t a0 = __float_as_uint(xs[(wrow + g    ) * XS_STRIDE + kk + tg    ]);
        uint32_t a1 = __float_as_uint(xs[(wrow + g + 8) * XS_STRIDE + kk + tg    ]);
        uint32_t a2 = __float_as_uint(xs[(wrow + g    ) * XS_STRIDE + kk + tg + 4]);
        uint32_t a3 = __float_as_uint(xs[(wrow + g + 8) * XS_STRIDE + kk + tg + 4]);
        #pragma unroll
        for (int nt = 0; nt < 16; nt++) {
            uint32_t b0 = __float_as_uint(ws[(kk + tg    ) * WS_STRIDE + nt * 8 + g]);
            uint32_t b1 = __float_as_uint(ws[(kk + tg + 4) * WS_STRIDE + nt * 8 + g]);
            asm volatile(
                "mma.sync.aligned.m16n8k8.row.col.f32.tf32.tf32.f32 "
                "{%0,%1,%2,%3}, {%4,%5,%6,%7}, {%8,%9}, {%0,%1,%2,%3};"
                : "+f"(acc[nt][0]), "+f"(acc[nt][1]), "+f"(acc[nt][2]), "+f"(acc[nt][3])
                : "r"(a0), "r"(a1), "r"(a2), "r"(a3), "r"(b0), "r"(b1));
        }
    }

    float* xw = reinterpret_cast<float*>(g_xw4);
    int r_lo = row0 + wrow + g;
    int r_hi = r_lo + 8;
    float d_lo = (r_lo < NN) ? g_dinv[r_lo] : 0.f;
    float d_hi = (r_hi < NN) ? g_dinv[r_hi] : 0.f;
    #pragma unroll
    for (int nt = 0; nt < 16; nt++) {
        int col = nt * 8 + 2 * tg;
        if (r_lo < NN) {
            *reinterpret_cast<float2*>(&xw[r_lo * DD + col]) =
                make_float2(acc[nt][0], acc[nt][1]);
            g_xwh2[r_lo * 64 + (col >> 1)] =
                __floats2half2_rn(acc[nt][0] * d_lo, acc[nt][1] * d_lo);
        }
        if (r_hi < NN) {
            *reinterpret_cast<float2*>(&xw[r_hi * DD + col]) =
                make_float2(acc[nt][2], acc[nt][3]);
            g_xwh2[r_hi * 64 + (col >> 1)] =
                __floats2half2_rn(acc[nt][2] * d_hi, acc[nt][3] * d_hi);
        }
    }
}

// ---------------------------------------------------------------------------
// K5: 512 threads / 64 nodes (4 nodes per warp).
//   Phase A: pure-sum fp16 gather, 1-ahead prefetch -> h (tf32, smem)
//   Phase B (warps 0-3): tensor-core MLP; Phase C (threads 0-63): dot
// ---------------------------------------------------------------------------
#define HS 132
#define SS 36

__device__ __forceinline__ void acc_row(float4& a, int row, int lane) {
    uint2 u = __ldg(reinterpret_cast<const uint2*>(&g_xwh2[row * 64 + lane * 2]));
    float2 fa = __half22float2(*reinterpret_cast<__half2*>(&u.x));
    float2 fb = __half22float2(*reinterpret_cast<__half2*>(&u.y));
    a.x += fa.x; a.y += fa.y; a.z += fb.x; a.w += fb.y;
}

__global__ __launch_bounds__(512) void k_aggmlp(const float* __restrict__ x,
                                                const float* __restrict__ b_gcn,
                                                const float* __restrict__ w1,
                                                const float* __restrict__ b1,
                                                const float* __restrict__ w2,
                                                const float* __restrict__ b2,
                                                const float* __restrict__ w3,
                                                const float* __restrict__ b3,
                                                float* __restrict__ out) {
    extern __shared__ float smem[];
    float* hs   = smem;                    // [64][HS]
    float* s1s  = smem + 64 * HS;          // [64][SS]
    float* s2s  = s1s + 64 * SS;           // [64][SS]
    int*   s_rs = reinterpret_cast<int*>(s2s + 64 * SS);  // [65]
    float* s_dv = reinterpret_cast<float*>(s_rs + 68);    // [64]

    const int tid  = threadIdx.x;
    const int lane = tid & 31;
    const int warp = tid >> 5;             // 0..15
    const int nbase = blockIdx.x * 64;

    if (tid < 64 && nbase + tid < NN) {
        g_deg[nbase + tid] = 0;            // for NEXT invocation
        s_dv[tid] = g_dinv[nbase + tid];
    }
    if (tid < 65 && nbase + tid <= NN) s_rs[tid] = g_rowstart[nbase + tid];
    __syncthreads();

    float4 bg = __ldg(&reinterpret_cast<const float4*>(b_gcn)[lane]);

    // ---- Phase A: 4 nodes per warp; 1-ahead srow prefetch ----
    const int r0 = warp * 4;
    int e0c = 0, cntc = 0, src = 0;
    if (nbase + r0 < NN) {
        e0c  = s_rs[r0];
        cntc = s_rs[r0 + 1] - e0c;
        src  = (lane < cntc) ? __ldg(&g_srow[e0c + lane]) : 0;
    }

    #pragma unroll 1
    for (int i = 0; i < 4; i++) {
        int r = r0 + i;
        int n = nbase + r;

        int e0n = 0, cntn = 0, srn = 0;
        if (i < 3 && nbase + r + 1 < NN) {
            e0n  = s_rs[r + 1];
            cntn = s_rs[r + 2] - e0n;
            srn  = (lane < cntn) ? __ldg(&g_srow[e0n + lane]) : 0;
        }

        if (n >= NN) {
            *reinterpret_cast<float4*>(&hs[r * HS + lane * 4]) =
                make_float4(0.f, 0.f, 0.f, 0.f);
            e0c = e0n; cntc = cntn; src = srn;
            continue;
        }

        float4 wv = g_xw4[n * 32 + lane];
        float4 xv = reinterpret_cast<const float4*>(x)[n * 32 + lane];
        float  d  = s_dv[r];

        float4 a0 = make_float4(0.f, 0.f, 0.f, 0.f);
        float4 a1 = make_float4(0.f, 0.f, 0.f, 0.f);
        float4 a2 = make_float4(0.f, 0.f, 0.f, 0.f);
        float4 a3 = make_float4(0.f, 0.f, 0.f, 0.f);

        int m = cntc < 32 ? cntc : 32;
        int j = 0;
        for (; j + 3 < m; j += 4) {
            int ra = __shfl_sync(0xFFFFFFFFu, src, j);
            int rb = __shfl_sync(0xFFFFFFFFu, src, j + 1);
            int rc = __shfl_sync(0xFFFFFFFFu, src, j + 2);
            int rd = __shfl_sync(0xFFFFFFFFu, src, j + 3);
            acc_row(a0, ra, lane);
            acc_row(a1, rb, lane);
            acc_row(a2, rc, lane);
            acc_row(a3, rd, lane);
        }
        for (; j < m; j++) {
            int ra = __shfl_sync(0xFFFFFFFFu, src, j);
            acc_row(a0, ra, lane);
        }
        for (int e = e0c + 32; e < e0c + cntc; e++)   // rare deg>32 tail
            acc_row(a0, g_srow[e], lane);

        a0.x += a1.x + a2.x + a3.x;
        a0.y += a1.y + a2.y + a3.y;
        a0.z += a1.z + a2.z + a3.z;
        a0.w += a1.w + a2.w + a3.w;

        float h0 = fmaxf(fmaf(d, a0.x, d * d * wv.x) + bg.x, 0.f) + xv.x;
        float h1 = fmaxf(fmaf(d, a0.y, d * d * wv.y) + bg.y, 0.f) + xv.y;
        float h2 = fmaxf(fmaf(d, a0.z, d * d * wv.z) + bg.z, 0.f) + xv.z;
        float h3 = fmaxf(fmaf(d, a0.w, d * d * wv.w) + bg.w, 0.f) + xv.w;

        *reinterpret_cast<float4*>(&hs[r * HS + lane * 4]) =
            make_float4(__uint_as_float(f2tf32(h0)), __uint_as_float(f2tf32(h1)),
                        __uint_as_float(f2tf32(h2)), __uint_as_float(f2tf32(h3)));

        e0c = e0n; cntc = cntn; src = srn;
    }
    __syncthreads();

    const int g  = lane >> 2;
    const int tg = lane & 3;

    // ---- Phase B1: layer1 [64x128]@[128x32] ----
    if (warp < 4) {
        const int m0 = warp * 16;
        float acc[4][4];
        #pragma unroll
        for (int nt = 0; nt < 4; nt++)
            #pragma unroll
            for (int q = 0; q < 4; q++) acc[nt][q] = 0.f;

        #pragma unroll
        for (int kk = 0; kk < DD; kk += 8) {
            uint32_t fa0 = __float_as_uint(hs[(m0 + g    ) * HS + kk + tg    ]);
            uint32_t fa1 = __float_as_uint(hs[(m0 + g + 8) * HS + kk + tg    ]);
            uint32_t fa2 = __float_as_uint(hs[(m0 + g    ) * HS + kk + tg + 4]);
            uint32_t fa3 = __float_as_uint(hs[(m0 + g + 8) * HS + kk + tg + 4]);
            #pragma unroll
            for (int nt = 0; nt < 4; nt++) {
                uint32_t b0 = f2tf32(__ldg(&w1[(kk + tg    ) * HH + nt * 8 + g]));
                uint32_t b1r = f2tf32(__ldg(&w1[(kk + tg + 4) * HH + nt * 8 + g]));
                asm volatile(
                    "mma.sync.aligned.m16n8k8.row.col.f32.tf32.tf32.f32 "
                    "{%0,%1,%2,%3}, {%4,%5,%6,%7}, {%8,%9}, {%0,%1,%2,%3};"
                    : "+f"(acc[nt][0]), "+f"(acc[nt][1]), "+f"(acc[nt][2]), "+f"(acc[nt][3])
                    : "r"(fa0), "r"(fa1), "r"(fa2), "r"(fa3), "r"(b0), "r"(b1r));
            }
        }
        #pragma unroll
        for (int nt = 0; nt < 4; nt++) {
            int c0 = nt * 8 + 2 * tg;
            float bb0 = __ldg(&b1[c0]);
            float bb1 = __ldg(&b1[c0 + 1]);
            s1s[(m0 + g    ) * SS + c0    ] = __uint_as_float(f2tf32(fmaxf(acc[nt][0] + bb0, 0.f)));
            s1s[(m0 + g    ) * SS + c0 + 1] = __uint_as_float(f2tf32(fmaxf(acc[nt][1] + bb1, 0.f)));
            s1s[(m0 + g + 8) * SS + c0    ] = __uint_as_float(f2tf32(fmaxf(acc[nt][2] + bb0, 0.f)));
            s1s[(m0 + g + 8) * SS + c0 + 1] = __uint_as_float(f2tf32(fmaxf(acc[nt][3] + bb1, 0.f)));
        }
    }
    __syncthreads();

    // ---- Phase B2: layer2 [64x32]@[32x32] ----
    if (warp < 4) {
        const int m0 = warp * 16;
        float acc[4][4];
        #pragma unroll
        for (int nt = 0; nt < 4; nt++)
            #pragma unroll
            for (int q = 0; q < 4; q++) acc[nt][q] = 0.f;

        #pragma unroll
        for (int kk = 0; kk < HH; kk += 8) {
            uint32_t fa0 = __float_as_uint(s1s[(m0 + g    ) * SS + kk + tg    ]);
            uint32_t fa1 = __float_as_uint(s1s[(m0 + g + 8) * SS + kk + tg    ]);
            uint32_t fa2 = __float_as_uint(s1s[(m0 + g    ) * SS + kk + tg + 4]);
            uint32_t fa3 = __float_as_uint(s1s[(m0 + g + 8) * SS + kk + tg + 4]);
            #pragma unroll
            for (int nt = 0; nt < 4; nt++) {
                uint32_t b0 = f2tf32(__ldg(&w2[(kk + tg    ) * HH + nt * 8 + g]));
                uint32_t b1r = f2tf32(__ldg(&w2[(kk + tg + 4) * HH + nt * 8 + g]));
                asm volatile(
                    "mma.sync.aligned.m16n8k8.row.col.f32.tf32.tf32.f32 "
                    "{%0,%1,%2,%3}, {%4,%5,%6,%7}, {%8,%9}, {%0,%1,%2,%3};"
                    : "+f"(acc[nt][0]), "+f"(acc[nt][1]), "+f"(acc[nt][2]), "+f"(acc[nt][3])
                    : "r"(fa0), "r"(fa1), "r"(fa2), "r"(fa3), "r"(b0), "r"(b1r));
            }
        }
        #pragma unroll
        for (int nt = 0; nt < 4; nt++) {
            int c0 = nt * 8 + 2 * tg;
            float bb0 = __ldg(&b2[c0]);
            float bb1 = __ldg(&b2[c0 + 1]);
            s2s[(m0 + g    ) * SS + c0    ] = fmaxf(acc[nt][0] + bb0, 0.f);
            s2s[(m0 + g    ) * SS + c0 + 1] = fmaxf(acc[nt][1] + bb1, 0.f);
            s2s[(m0 + g + 8) * SS + c0    ] = fmaxf(acc[nt][2] + bb0, 0.f);
            s2s[(m0 + g + 8) * SS + c0 + 1] = fmaxf(acc[nt][3] + bb1, 0.f);
        }
    }
    __syncthreads();

    // ---- Phase C: layer3 ----
    if (tid < 64) {
        int n = nbase + tid;
        if (n < NN) {
            float p = 0.f;
            #pragma unroll
            for (int j = 0; j < HH; j++)
                p = fmaf(s2s[tid * SS + j], __ldg(&w3[j]), p);
            out[n] = p + __ldg(&b3[0]);
        }
    }
}

// ---------------------------------------------------------------------------
// launch — count+scan1 first; GEMM (needs dinv) overlaps scan23+scatter
// ---------------------------------------------------------------------------
extern "C" void kernel_launch(void* const* d_in, const int* in_sizes, int n_in,
                              void* d_out, int out_size) {
    const float* x     = (const float*)d_in[0];
    const int*   ei    = (const int*)  d_in[1];
    const float* W_gcn = (const float*)d_in[2];
    const float* b_gcn = (const float*)d_in[3];
    const float* w1    = (const float*)d_in[4];
    const float* b1    = (const float*)d_in[5];
    const float* w2    = (const float*)d_in[6];
    const float* b2    = (const float*)d_in[7];
    const float* w3    = (const float*)d_in[8];
    const float* b3    = (const float*)d_in[9];
    float* out = (float*)d_out;

    const int smem_gemm = (64 * XS_STRIDE + 128 * WS_STRIDE) * sizeof(float);
    const int smem_agg  = (64 * HS + 2 * 64 * SS) * sizeof(float) + 68 * 4 + 64 * 4;
    static cudaStream_t s1 = nullptr;
    static cudaEvent_t evDinv, evGemm;
    if (s1 == nullptr) {
        cudaFuncSetAttribute(k_gemm_mma, cudaFuncAttributeMaxDynamicSharedMemorySize,
                             smem_gemm);
        cudaFuncSetAttribute(k_aggmlp, cudaFuncAttributeMaxDynamicSharedMemorySize,
                             smem_agg);
        cudaStreamCreateWithFlags(&s1, cudaStreamNonBlocking);
        cudaEventCreateWithFlags(&evDinv, cudaEventDisableTiming);
        cudaEventCreateWithFlags(&evGemm, cudaEventDisableTiming);
    }

    const int nblk = (NN + 255) / 256;  // 196

    k_count  <<<(EE + 255) / 256, 256>>>(ei);
    k_scan1  <<<nblk, 256>>>();
    cudaEventRecord(evDinv, 0);                 // dinv ready

    // side stream: GEMM with premultiplied fp16 epilogue
    cudaStreamWaitEvent(s1, evDinv, 0);
    k_gemm_mma<<<(NN + 63) / 64, 128, smem_gemm, s1>>>(x, W_gcn);
    cudaEventRecord(evGemm, s1);

    // main stream: finish CSR build in parallel with the GEMM
    k_scan23 <<<nblk, 256>>>(nblk);
    k_scatter<<<(EE + 255) / 256, 256>>>(ei);

    cudaStreamWaitEvent(0, evGemm, 0);
    k_aggmlp <<<(NN + 63) / 64, 512, smem_agg>>>(x, b_gcn, w1, b1, w2, b2, w3, b3, out);
}